// round 2
// baseline (speedup 1.0000x reference)
#include <cuda_runtime.h>
#include <math.h>

#define BATCH 2
#define SEQ   2048
#define DM    1024
#define NHEAD 16
#define HS    64
#define FQ    256
#define BN3   3072   /* 3*NHEAD*HS */

// ---------------- scratch (device globals; no allocations allowed) ----------
__device__ float g_Q[BATCH*NHEAD*SEQ*HS];
__device__ float g_K[BATCH*NHEAD*SEQ*HS];
__device__ float g_V[BATCH*NHEAD*SEQ*HS];
__device__ float g_emb[NHEAD*SEQ*HS];
__device__ float g_S[(size_t)BATCH*NHEAD*SEQ*SEQ];   // 512 MB score/prob matrix
__device__ float g_O[BATCH*SEQ*NHEAD*HS];

// ---------------- 1) QKV projection: (4096x1024) @ (1024x3072) --------------
// C[m, c] = sum_x inp[m,x] * w[x,c] * qkv_scale ; scatter into Q/K/V [b,n,s,h]
__global__ __launch_bounds__(256) void qkv_kernel(
    const float* __restrict__ inp, const float* __restrict__ w,
    const float* __restrict__ qb)
{
    __shared__ float Ast[16][65];   // A tile transposed [k][m]
    __shared__ float Bs[16][64];    // B tile [k][n]
    const int tid = threadIdx.x;
    const int tx = tid & 15, ty = tid >> 4;
    const int m0 = blockIdx.y * 64, n0 = blockIdx.x * 64;

    float acc[4][4] = {};
    for (int k0 = 0; k0 < DM; k0 += 16) {
        #pragma unroll
        for (int t = 0; t < 4; t++) {
            int e = tid + t * 256;
            Ast[e & 15][e >> 4] = inp[(size_t)(m0 + (e >> 4)) * DM + k0 + (e & 15)];
            Bs[e >> 6][e & 63]  = w[(size_t)(k0 + (e >> 6)) * BN3 + n0 + (e & 63)];
        }
        __syncthreads();
        #pragma unroll
        for (int kk = 0; kk < 16; kk++) {
            float a[4], b[4];
            #pragma unroll
            for (int i = 0; i < 4; i++) a[i] = Ast[kk][ty * 4 + i];
            #pragma unroll
            for (int j = 0; j < 4; j++) b[j] = Bs[kk][tx * 4 + j];
            #pragma unroll
            for (int i = 0; i < 4; i++)
                #pragma unroll
                for (int j = 0; j < 4; j++) acc[i][j] += a[i] * b[j];
        }
        __syncthreads();
    }

    const float qscale = powf(3.0f * DM * NHEAD * HS, -0.25f);
    #pragma unroll
    for (int i = 0; i < 4; i++) {
        int m = m0 + ty * 4 + i;
        int b = m >> 11;            // m / SEQ
        int s = m & (SEQ - 1);
        #pragma unroll
        for (int j = 0; j < 4; j++) {
            int c = n0 + tx * 4 + j;
            int A = c >> 10;
            int n = (c >> 6) & (NHEAD - 1);
            int h = c & (HS - 1);
            float v = acc[i][j] * qscale;
            size_t dst = ((size_t)(b * NHEAD + n) * SEQ + s) * HS + h;
            if (A == 0)      g_Q[dst] = v + qb[n * HS + h];
            else if (A == 1) g_K[dst] = v;
            else             g_V[dst] = v;
        }
    }
}

// ---------------- 2) relative-position embedding table ----------------------
// emb[n, s, h] = sum_f sqrt(2)*sinusoid(s,f) * positional[f,n,h] * FQ^-0.5
__global__ __launch_bounds__(256) void emb_kernel(const float* __restrict__ pos)
{
    __shared__ float ssin[FQ];
    const int s = blockIdx.x;
    const int tid = threadIdx.x;
    {
        int f = tid;   // 256 threads == FQ
        double inv = pow(10000.0, -(double)((f >> 1) * 2) / (double)FQ);
        double ang = (double)s * inv;
        double v = (f & 1) ? cos(ang) : sin(ang);
        ssin[f] = (float)(1.4142135623730951 * v);
    }
    __syncthreads();

    int c4 = tid * 4;    // 4 consecutive (n,h) outputs
    float a0 = 0.f, a1 = 0.f, a2 = 0.f, a3 = 0.f;
    for (int f = 0; f < FQ; f++) {
        float4 p = *reinterpret_cast<const float4*>(&pos[(size_t)f * (NHEAD * HS) + c4]);
        float sv = ssin[f];
        a0 += sv * p.x; a1 += sv * p.y; a2 += sv * p.z; a3 += sv * p.w;
    }
    const float pscale = 0.0625f;   // FQ^-0.5
    int n = c4 >> 6, h = c4 & 63;
    size_t base = ((size_t)n * SEQ + s) * HS + h;
    g_emb[base + 0] = a0 * pscale;
    g_emb[base + 1] = a1 * pscale;
    g_emb[base + 2] = a2 * pscale;
    g_emb[base + 3] = a3 * pscale;
}

// ---------------- 3) scores: content + relative-positional -------------------
// S[b,n,q,k] = ( Q.K^T + (Q @ emb^T)[q, q-k] ) * HS^-0.5 , k <= q
extern __shared__ float sc_smem[];
__global__ __launch_bounds__(256, 2) void scores_kernel()
{
    const int kt = blockIdx.x, qt = blockIdx.y;
    if (kt > qt) return;
    const int bn = blockIdx.z;
    const int q0 = qt * 64, k0 = kt * 64;

    float* sQ = sc_smem;             // [64][65]
    float* sK = sQ + 64 * 65;        // [64][65]
    float* sE = sK + 64 * 65;        // [128][65]
    float* sP = sE + 128 * 65;       // [64][129]

    const float* Qg = g_Q + (size_t)bn * SEQ * HS;
    const float* Kg = g_K + (size_t)bn * SEQ * HS;
    const int n = bn & (NHEAD - 1);
    const float* Eg = g_emb + (size_t)n * SEQ * HS;

    const int tid = threadIdx.x;
    const int tx = tid & 15, ty = tid >> 4;

    #pragma unroll
    for (int t = 0; t < 16; t++) {
        int e = tid + t * 256;
        int r = e >> 6, c = e & 63;
        sQ[r * 65 + c] = Qg[(size_t)(q0 + r) * HS + c];
        sK[r * 65 + c] = Kg[(size_t)(k0 + r) * HS + c];
    }
    int dlo = q0 - k0 - 63; if (dlo < 0) dlo = 0;
    #pragma unroll
    for (int t = 0; t < 32; t++) {
        int e = tid + t * 256;
        int r = e >> 6, c = e & 63;
        int d = dlo + r;
        sE[r * 65 + c] = (d < SEQ) ? Eg[(size_t)d * HS + c] : 0.f;
    }
    __syncthreads();

    // content: 4x4 per thread over full H=64
    float acc[4][4] = {};
    #pragma unroll 8
    for (int h = 0; h < HS; h++) {
        float a[4], b[4];
        #pragma unroll
        for (int i = 0; i < 4; i++) a[i] = sQ[(ty * 4 + i) * 65 + h];
        #pragma unroll
        for (int j = 0; j < 4; j++) b[j] = sK[(tx * 4 + j) * 65 + h];
        #pragma unroll
        for (int i = 0; i < 4; i++)
            #pragma unroll
            for (int j = 0; j < 4; j++) acc[i][j] += a[i] * b[j];
    }

    // positional panel: P[64 q][128 d] = sQ @ sE^T, 4x8 per thread
    float pp[4][8] = {};
    #pragma unroll 8
    for (int h = 0; h < HS; h++) {
        float a[4], ev[8];
        #pragma unroll
        for (int i = 0; i < 4; i++) a[i] = sQ[(ty * 4 + i) * 65 + h];
        #pragma unroll
        for (int j = 0; j < 8; j++) ev[j] = sE[(tx * 8 + j) * 65 + h];
        #pragma unroll
        for (int i = 0; i < 4; i++)
            #pragma unroll
            for (int j = 0; j < 8; j++) pp[i][j] += a[i] * ev[j];
    }
    #pragma unroll
    for (int i = 0; i < 4; i++)
        #pragma unroll
        for (int j = 0; j < 8; j++)
            sP[(ty * 4 + i) * 129 + tx * 8 + j] = pp[i][j];
    __syncthreads();

    // combine via the diagonal gather and write
    float* Srow = g_S + (size_t)bn * SEQ * SEQ;
    #pragma unroll
    for (int i = 0; i < 4; i++) {
        int q = q0 + ty * 4 + i;
        #pragma unroll
        for (int j = 0; j < 4; j++) {
            int k = k0 + tx * 4 + j;
            float v;
            if (k > q) v = -1e9f;
            else       v = (acc[i][j] + sP[(ty * 4 + i) * 129 + (q - k - dlo)]) * 0.125f;
            Srow[(size_t)q * SEQ + k] = v;
        }
    }
}

// ---------------- 4) row softmax (in place), zero-pad to 64 ------------------
__global__ __launch_bounds__(256) void softmax_kernel()
{
    const int q = blockIdx.x;
    const int bn = blockIdx.y;
    float* row = g_S + ((size_t)bn * SEQ + q) * SEQ;
    const int len = q + 1;
    const int tid = threadIdx.x;

    float v[8];
    float m = -1e30f;
    #pragma unroll
    for (int t = 0; t < 8; t++) {
        int k = tid + t * 256;
        if (k < len) { v[t] = row[k]; m = fmaxf(m, v[t]); }
    }
    __shared__ float red[40];
    #pragma unroll
    for (int o = 16; o > 0; o >>= 1) m = fmaxf(m, __shfl_xor_sync(0xffffffffu, m, o));
    if ((tid & 31) == 0) red[tid >> 5] = m;
    __syncthreads();
    if (tid == 0) {
        float mm = red[0];
        #pragma unroll
        for (int wdx = 1; wdx < 8; wdx++) mm = fmaxf(mm, red[wdx]);
        red[32] = mm;
    }
    __syncthreads();
    const float M = red[32];

    float s = 0.f;
    #pragma unroll
    for (int t = 0; t < 8; t++) {
        int k = tid + t * 256;
        if (k < len) { v[t] = __expf(v[t] - M); s += v[t]; }
    }
    #pragma unroll
    for (int o = 16; o > 0; o >>= 1) s += __shfl_xor_sync(0xffffffffu, s, o);
    if ((tid & 31) == 0) red[8 + (tid >> 5)] = s;
    __syncthreads();
    if (tid == 0) {
        float ss = 0.f;
        #pragma unroll
        for (int wdx = 0; wdx < 8; wdx++) ss += red[8 + wdx];
        red[33] = 1.f / ss;
    }
    __syncthreads();
    const float inv = red[33];

    #pragma unroll
    for (int t = 0; t < 8; t++) {
        int k = tid + t * 256;
        if (k < len) row[k] = v[t] * inv;
    }
    const int padEnd = ((q >> 6) + 1) << 6;
    for (int k = len + tid; k < padEnd; k += 256) row[k] = 0.f;
}

// ---------------- 5) O = P @ V  (only k-tiles <= diagonal) -------------------
__global__ __launch_bounds__(256) void av_kernel()
{
    __shared__ float sP[64][65];
    __shared__ float sV[64][65];
    const int qt = blockIdx.x, bn = blockIdx.y;
    const int tid = threadIdx.x;
    const int tx = tid & 15, ty = tid >> 4;
    const int q0 = qt * 64;

    const float* Pg = g_S + (size_t)bn * SEQ * SEQ;
    const float* Vg = g_V + (size_t)bn * SEQ * HS;

    float acc[4][4] = {};
    for (int kt = 0; kt <= qt; kt++) {
        const int k0 = kt * 64;
        #pragma unroll
        for (int t = 0; t < 16; t++) {
            int e = tid + t * 256;
            int r = e >> 6, c = e & 63;
            sP[r][c] = Pg[(size_t)(q0 + r) * SEQ + k0 + c];
            sV[r][c] = Vg[(size_t)(k0 + r) * HS + c];
        }
        __syncthreads();
        #pragma unroll 8
        for (int kk = 0; kk < 64; kk++) {
            float a[4], b[4];
            #pragma unroll
            for (int i = 0; i < 4; i++) a[i] = sP[ty * 4 + i][kk];
            #pragma unroll
            for (int j = 0; j < 4; j++) b[j] = sV[kk][tx * 4 + j];
            #pragma unroll
            for (int i = 0; i < 4; i++)
                #pragma unroll
                for (int j = 0; j < 4; j++) acc[i][j] += a[i] * b[j];
        }
        __syncthreads();
    }

    const int b = bn >> 4, n = bn & (NHEAD - 1);
    #pragma unroll
    for (int i = 0; i < 4; i++) {
        int q = q0 + ty * 4 + i;
        #pragma unroll
        for (int j = 0; j < 4; j++) {
            int h = tx * 4 + j;
            g_O[(((size_t)b * SEQ + q) * NHEAD + n) * HS + h] = acc[i][j];
        }
    }
}

// ---------------- 6) out = O @ (out_kernel * scale) + bias -------------------
__global__ __launch_bounds__(256) void proj_kernel(
    const float* __restrict__ wk, const float* __restrict__ bias,
    float* __restrict__ out)
{
    __shared__ float Ast[16][65];
    __shared__ float Bs[16][64];
    const int tid = threadIdx.x;
    const int tx = tid & 15, ty = tid >> 4;
    const int m0 = blockIdx.y * 64, n0 = blockIdx.x * 64;

    float acc[4][4] = {};
    for (int k0 = 0; k0 < DM; k0 += 16) {
        #pragma unroll
        for (int t = 0; t < 4; t++) {
            int e = tid + t * 256;
            Ast[e & 15][e >> 4] = g_O[(size_t)(m0 + (e >> 4)) * DM + k0 + (e & 15)];
            Bs[e >> 6][e & 63]  = wk[(size_t)(k0 + (e >> 6)) * DM + n0 + (e & 63)];
        }
        __syncthreads();
        #pragma unroll
        for (int kk = 0; kk < 16; kk++) {
            float a[4], b[4];
            #pragma unroll
            for (int i = 0; i < 4; i++) a[i] = Ast[kk][ty * 4 + i];
            #pragma unroll
            for (int j = 0; j < 4; j++) b[j] = Bs[kk][tx * 4 + j];
            #pragma unroll
            for (int i = 0; i < 4; i++)
                #pragma unroll
                for (int j = 0; j < 4; j++) acc[i][j] += a[i] * b[j];
        }
        __syncthreads();
    }

    const float okscale = 0.03125f;   // (1024*1024)^-0.25 = 2^-5 exact
    #pragma unroll
    for (int i = 0; i < 4; i++) {
        int m = m0 + ty * 4 + i;
        #pragma unroll
        for (int j = 0; j < 4; j++) {
            int c = n0 + tx * 4 + j;
            out[(size_t)m * DM + c] = acc[i][j] * okscale + bias[c];
        }
    }
}

// ---------------- launcher ---------------------------------------------------
extern "C" void kernel_launch(void* const* d_in, const int* in_sizes, int n_in,
                              void* d_out, int out_size)
{
    const float* inp = (const float*)d_in[0];   // (2, 2048, 1024)
    const float* qkv = (const float*)d_in[1];   // (1024, 3, 16, 64)
    const float* qb  = (const float*)d_in[2];   // (16, 64)
    const float* pos = (const float*)d_in[3];   // (256, 16, 64)
    const float* wk  = (const float*)d_in[4];   // (1024, 1024)
    const float* ob  = (const float*)d_in[5];   // (1024,)
    float* out = (float*)d_out;                 // (2, 2048, 1024)

    const int SC_SMEM = (64 * 65 + 64 * 65 + 128 * 65 + 64 * 129) * 4;  // 99584 B
    cudaFuncSetAttribute(scores_kernel,
                         cudaFuncAttributeMaxDynamicSharedMemorySize, SC_SMEM);

    qkv_kernel<<<dim3(BN3 / 64, (BATCH * SEQ) / 64), 256>>>(inp, qkv, qb);
    emb_kernel<<<SEQ, 256>>>(pos);
    scores_kernel<<<dim3(SEQ / 64, SEQ / 64, BATCH * NHEAD), 256, SC_SMEM>>>();
    softmax_kernel<<<dim3(SEQ, BATCH * NHEAD), 256>>>();
    av_kernel<<<dim3(SEQ / 64, BATCH * NHEAD), 256>>>();
    proj_kernel<<<dim3(DM / 64, (BATCH * SEQ) / 64), 256>>>(wk, ob, out);
}

// round 4
// speedup vs baseline: 2.4642x; 2.4642x over previous
#include <cuda_runtime.h>
#include <math.h>
#include <stdint.h>

#define BATCH 2
#define SEQ   2048
#define DM    1024
#define NHEAD 16
#define HS    64
#define FQ    256
#define BN3   3072   /* 3*NHEAD*HS */

// ---------------- scratch (device globals; no allocations allowed) ----------
__device__ float g_Q[BATCH*NHEAD*SEQ*HS];
__device__ float g_K[BATCH*NHEAD*SEQ*HS];
__device__ float g_V[BATCH*NHEAD*SEQ*HS];
__device__ float g_emb[NHEAD*SEQ*HS];
__device__ float g_S[(size_t)BATCH*NHEAD*SEQ*SEQ];   // 512 MB score/prob matrix
__device__ float g_O[BATCH*SEQ*NHEAD*HS];

// ---------------- tf32 mma helpers ------------------------------------------
__device__ __forceinline__ uint32_t f2t(float x) {
    uint32_t r; asm("cvt.rna.tf32.f32 %0, %1;" : "=r"(r) : "f"(x)); return r;
}
__device__ __forceinline__ void mma8(float c[4], const uint32_t a[4], const uint32_t b[2]) {
    asm volatile(
      "mma.sync.aligned.m16n8k8.row.col.f32.tf32.tf32.f32 "
      "{%0,%1,%2,%3}, {%4,%5,%6,%7}, {%8,%9}, {%0,%1,%2,%3};"
      : "+f"(c[0]), "+f"(c[1]), "+f"(c[2]), "+f"(c[3])
      : "r"(a[0]), "r"(a[1]), "r"(a[2]), "r"(a[3]), "r"(b[0]), "r"(b[1]));
}

// ---------------- 1) QKV projection: (4096x1024) @ (1024x3072), tf32 mma ----
__global__ __launch_bounds__(256) void qkv_kernel(
    const float* __restrict__ inp, const float* __restrict__ w,
    const float* __restrict__ qb)
{
    __shared__ uint32_t sA[128][20];    // [m][k], stride 20: conflict-free A frags
    __shared__ uint32_t sB[16][136];    // [k][n], stride 136 (==8 mod 32): conflict-free B frags
    const int tid = threadIdx.x, lane = tid & 31, wid = tid >> 5;
    const int g = lane >> 2, tg = lane & 3;
    const int warpN = wid & 1, warpM = wid >> 1;     // 4 x 2 warp grid, warp tile 32x64
    const int m0 = blockIdx.y * 128, n0 = blockIdx.x * 128;

    float acc[2][8][4] = {};
    for (int k0 = 0; k0 < DM; k0 += 16) {
        #pragma unroll
        for (int t = 0; t < 2; t++) {
            int e = tid + t * 256;
            int r = e >> 2, c = (e & 3) * 4;
            float4 v = *(const float4*)&inp[(size_t)(m0 + r) * DM + k0 + c];
            sA[r][c] = f2t(v.x); sA[r][c+1] = f2t(v.y);
            sA[r][c+2] = f2t(v.z); sA[r][c+3] = f2t(v.w);
            int rb = e >> 5, cb = (e & 31) * 4;
            float4 u = *(const float4*)&w[(size_t)(k0 + rb) * BN3 + n0 + cb];
            sB[rb][cb] = f2t(u.x); sB[rb][cb+1] = f2t(u.y);
            sB[rb][cb+2] = f2t(u.z); sB[rb][cb+3] = f2t(u.w);
        }
        __syncthreads();
        #pragma unroll
        for (int ks = 0; ks < 16; ks += 8) {
            uint32_t af[2][4];
            #pragma unroll
            for (int i = 0; i < 2; i++) {
                int mr = warpM * 32 + i * 16;
                af[i][0] = sA[mr + g    ][ks + tg    ];
                af[i][1] = sA[mr + g + 8][ks + tg    ];
                af[i][2] = sA[mr + g    ][ks + tg + 4];
                af[i][3] = sA[mr + g + 8][ks + tg + 4];
            }
            #pragma unroll
            for (int j = 0; j < 8; j++) {
                int nc = warpN * 64 + j * 8 + g;
                uint32_t bf[2] = { sB[ks + tg][nc], sB[ks + tg + 4][nc] };
                #pragma unroll
                for (int i = 0; i < 2; i++) mma8(acc[i][j], af[i], bf);
            }
        }
        __syncthreads();
    }

    const float qscale = powf(3.0f * DM * NHEAD * HS, -0.25f);
    #pragma unroll
    for (int i = 0; i < 2; i++) {
        #pragma unroll
        for (int j = 0; j < 8; j++) {
            #pragma unroll
            for (int cr = 0; cr < 4; cr++) {
                int m = m0 + warpM * 32 + i * 16 + g + (cr >> 1) * 8;
                int c = n0 + warpN * 64 + j * 8 + tg * 2 + (cr & 1);
                int b = m >> 11, s = m & (SEQ - 1);
                int A = c >> 10, n = (c >> 6) & 15, h = c & 63;
                float v = acc[i][j][cr] * qscale;
                size_t dst = ((size_t)(b * NHEAD + n) * SEQ + s) * HS + h;
                if (A == 0)      g_Q[dst] = v + qb[n * HS + h];
                else if (A == 1) g_K[dst] = v;
                else             g_V[dst] = v;
            }
        }
    }
}

// ---------------- 2) relative-position embedding table ----------------------
__global__ __launch_bounds__(256) void emb_kernel(const float* __restrict__ pos)
{
    __shared__ float ssin[FQ];
    const int s = blockIdx.x;
    const int tid = threadIdx.x;
    {
        int f = tid;
        double inv = pow(10000.0, -(double)((f >> 1) * 2) / (double)FQ);
        double ang = (double)s * inv;
        double v = (f & 1) ? cos(ang) : sin(ang);
        ssin[f] = (float)(1.4142135623730951 * v);
    }
    __syncthreads();

    int c4 = tid * 4;
    float a0 = 0.f, a1 = 0.f, a2 = 0.f, a3 = 0.f;
    for (int f = 0; f < FQ; f++) {
        float4 p = *reinterpret_cast<const float4*>(&pos[(size_t)f * (NHEAD * HS) + c4]);
        float sv = ssin[f];
        a0 += sv * p.x; a1 += sv * p.y; a2 += sv * p.z; a3 += sv * p.w;
    }
    const float pscale = 0.0625f;
    int n = c4 >> 6, h = c4 & 63;
    size_t base = ((size_t)n * SEQ + s) * HS + h;
    g_emb[base + 0] = a0 * pscale;
    g_emb[base + 1] = a1 * pscale;
    g_emb[base + 2] = a2 * pscale;
    g_emb[base + 3] = a3 * pscale;
}

// ---------------- 3) scores: fused content+positional 64x192 tf32 GEMM ------
// S[b,n,q,k] = ( Q.K^T + (Q @ emb^T)[q, q-k] ) * HS^-0.5 , k <= q
extern __shared__ uint32_t sc_u[];
__global__ __launch_bounds__(256) void scores_kernel()
{
    const int kt = blockIdx.x, qt = blockIdx.y;
    if (kt > qt) return;
    const int bn = blockIdx.z;
    const int q0 = qt * 64, k0 = kt * 64;

    uint32_t* sQ  = sc_u;             // [64][72]   (tf32 bits)
    uint32_t* sKE = sc_u + 64 * 72;   // [192][72]  rows 0..63 = K, 64..191 = E window
    float* sC = (float*)sc_u;                 // [64][72]  (aliases sQ, stage 2)
    float* sP = (float*)sc_u + 64 * 72;       // [64][132] (aliases sKE, stage 2)

    const float* Qg = g_Q + (size_t)bn * SEQ * HS;
    const float* Kg = g_K + (size_t)bn * SEQ * HS;
    const int hd = bn & (NHEAD - 1);
    const float* Eg = g_emb + (size_t)hd * SEQ * HS;

    const int tid = threadIdx.x, lane = tid & 31, wid = tid >> 5;
    const int g = lane >> 2, tg = lane & 3;
    const int warpM = wid & 1, warpN = wid >> 1;   // 2 x 4 warp grid, warp tile 32x48

    int dlo = q0 - k0 - 63; if (dlo < 0) dlo = 0;

    #pragma unroll
    for (int t = 0; t < 4; t++) {
        int e = tid + t * 256;
        int r = e >> 4, c = (e & 15) * 4;
        float4 v = *(const float4*)&Qg[(size_t)(q0 + r) * HS + c];
        sQ[r * 72 + c] = f2t(v.x); sQ[r * 72 + c + 1] = f2t(v.y);
        sQ[r * 72 + c + 2] = f2t(v.z); sQ[r * 72 + c + 3] = f2t(v.w);
    }
    #pragma unroll
    for (int t = 0; t < 12; t++) {
        int e = tid + t * 256;
        int r = e >> 4, c = (e & 15) * 4;
        float4 v;
        if (r < 64) {
            v = *(const float4*)&Kg[(size_t)(k0 + r) * HS + c];
        } else {
            int d = dlo + r - 64;
            if (d < SEQ) v = *(const float4*)&Eg[(size_t)d * HS + c];
            else         v = make_float4(0.f, 0.f, 0.f, 0.f);
        }
        sKE[r * 72 + c] = f2t(v.x); sKE[r * 72 + c + 1] = f2t(v.y);
        sKE[r * 72 + c + 2] = f2t(v.z); sKE[r * 72 + c + 3] = f2t(v.w);
    }
    __syncthreads();

    float acc[2][6][4] = {};
    #pragma unroll
    for (int ks = 0; ks < HS; ks += 8) {
        uint32_t af[2][4];
        #pragma unroll
        for (int i = 0; i < 2; i++) {
            int mr = warpM * 32 + i * 16;
            af[i][0] = sQ[(mr + g    ) * 72 + ks + tg    ];
            af[i][1] = sQ[(mr + g + 8) * 72 + ks + tg    ];
            af[i][2] = sQ[(mr + g    ) * 72 + ks + tg + 4];
            af[i][3] = sQ[(mr + g + 8) * 72 + ks + tg + 4];
        }
        #pragma unroll
        for (int j = 0; j < 6; j++) {
            int nc = warpN * 48 + j * 8 + g;
            uint32_t bf[2] = { sKE[nc * 72 + ks + tg], sKE[nc * 72 + ks + tg + 4] };
            #pragma unroll
            for (int i = 0; i < 2; i++) mma8(acc[i][j], af[i], bf);
        }
    }
    __syncthreads();   // everyone done reading sQ/sKE; now alias as sC/sP

    #pragma unroll
    for (int i = 0; i < 2; i++) {
        #pragma unroll
        for (int j = 0; j < 6; j++) {
            #pragma unroll
            for (int cr = 0; cr < 4; cr++) {
                int row = warpM * 32 + i * 16 + g + (cr >> 1) * 8;
                int col = warpN * 48 + j * 8 + tg * 2 + (cr & 1);
                float v = acc[i][j][cr];
                if (col < 64) sC[row * 72 + col] = v;
                else          sP[row * 132 + (col - 64)] = v;
            }
        }
    }
    __syncthreads();

    // diagonal gather + mask + scale + write
    const int tx = tid & 15, ty = tid >> 4;
    float* Srow = g_S + (size_t)bn * SEQ * SEQ;
    #pragma unroll
    for (int i = 0; i < 4; i++) {
        int q = q0 + ty * 4 + i;
        #pragma unroll
        for (int j = 0; j < 4; j++) {
            int k = k0 + tx * 4 + j;
            float v;
            if (k > q) v = -1e9f;
            else       v = (sC[(ty * 4 + i) * 72 + (tx * 4 + j)]
                          + sP[(ty * 4 + i) * 132 + (q - k - dlo)]) * 0.125f;
            Srow[(size_t)q * SEQ + k] = v;
        }
    }
}

// ---------------- 4) row softmax (in place, vectorized) ----------------------
// Masked (-1e9) entries inside the diagonal tile exp to exactly 0, so we can
// process the whole 64-padded row unconditionally and the pad comes out 0.
__global__ __launch_bounds__(256) void softmax_kernel()
{
    const int q = blockIdx.x;
    const int bn = blockIdx.y;
    float4* row4 = (float4*)(g_S + ((size_t)bn * SEQ + q) * SEQ);
    const int n4 = (((q >> 6) + 1) << 6) >> 2;   // padEnd / 4 (<= 512)
    const int tid = threadIdx.x;

    __shared__ float red[32];
    float4 v[2];
    float m = -1e30f;
    #pragma unroll
    for (int t = 0; t < 2; t++) {
        int k = tid + t * 256;
        if (k < n4) {
            v[t] = row4[k];
            m = fmaxf(m, fmaxf(fmaxf(v[t].x, v[t].y), fmaxf(v[t].z, v[t].w)));
        }
    }
    #pragma unroll
    for (int o = 16; o > 0; o >>= 1) m = fmaxf(m, __shfl_xor_sync(0xffffffffu, m, o));
    if ((tid & 31) == 0) red[tid >> 5] = m;
    __syncthreads();
    if (tid < 32) {
        float mm = (tid < 8) ? red[tid] : -1e30f;
        #pragma unroll
        for (int o = 4; o > 0; o >>= 1) mm = fmaxf(mm, __shfl_xor_sync(0xffffffffu, mm, o));
        if (tid == 0) red[16] = mm;
    }
    __syncthreads();
    const float M = red[16];

    float s = 0.f;
    #pragma unroll
    for (int t = 0; t < 2; t++) {
        int k = tid + t * 256;
        if (k < n4) {
            v[t].x = __expf(v[t].x - M); v[t].y = __expf(v[t].y - M);
            v[t].z = __expf(v[t].z - M); v[t].w = __expf(v[t].w - M);
            s += (v[t].x + v[t].y) + (v[t].z + v[t].w);
        }
    }
    #pragma unroll
    for (int o = 16; o > 0; o >>= 1) s += __shfl_xor_sync(0xffffffffu, s, o);
    if ((tid & 31) == 0) red[8 + (tid >> 5)] = s;
    __syncthreads();
    if (tid < 32) {
        float ss = (tid < 8) ? red[8 + tid] : 0.f;
        #pragma unroll
        for (int o = 4; o > 0; o >>= 1) ss += __shfl_xor_sync(0xffffffffu, ss, o);
        if (tid == 0) red[17] = 1.f / ss;
    }
    __syncthreads();
    const float inv = red[17];

    #pragma unroll
    for (int t = 0; t < 2; t++) {
        int k = tid + t * 256;
        if (k < n4) {
            v[t].x *= inv; v[t].y *= inv; v[t].z *= inv; v[t].w *= inv;
            row4[k] = v[t];
        }
    }
}

// ---------------- 5) O = P @ V  (tf32 mma, k-tiles <= diagonal) --------------
__global__ __launch_bounds__(256) void av_kernel()
{
    __shared__ uint32_t sPb[64][72];   // [q][k]
    __shared__ uint32_t sV [64][72];   // [k][h]
    const int qt = blockIdx.x, bn = blockIdx.y;
    const int tid = threadIdx.x, lane = tid & 31, wid = tid >> 5;
    const int g = lane >> 2, tg = lane & 3;
    const int warpM = wid & 3, warpN = wid >> 2;   // 4 x 2 warp grid, warp tile 16x32
    const int q0 = qt * 64;

    const float* Pg = g_S + (size_t)bn * SEQ * SEQ;
    const float* Vg = g_V + (size_t)bn * SEQ * HS;

    float acc[4][4] = {};
    for (int kt = 0; kt <= qt; kt++) {
        const int k0 = kt * 64;
        #pragma unroll
        for (int t = 0; t < 4; t++) {
            int e = tid + t * 256;
            int r = e >> 4, c = (e & 15) * 4;
            float4 v = *(const float4*)&Pg[(size_t)(q0 + r) * SEQ + k0 + c];
            sPb[r][c] = f2t(v.x); sPb[r][c+1] = f2t(v.y);
            sPb[r][c+2] = f2t(v.z); sPb[r][c+3] = f2t(v.w);
            float4 u = *(const float4*)&Vg[(size_t)(k0 + r) * HS + c];
            sV[r][c] = f2t(u.x); sV[r][c+1] = f2t(u.y);
            sV[r][c+2] = f2t(u.z); sV[r][c+3] = f2t(u.w);
        }
        __syncthreads();
        #pragma unroll
        for (int ks = 0; ks < 64; ks += 8) {
            uint32_t af[4];
            int mr = warpM * 16;
            af[0] = sPb[mr + g    ][ks + tg    ];
            af[1] = sPb[mr + g + 8][ks + tg    ];
            af[2] = sPb[mr + g    ][ks + tg + 4];
            af[3] = sPb[mr + g + 8][ks + tg + 4];
            #pragma unroll
            for (int j = 0; j < 4; j++) {
                int nc = warpN * 32 + j * 8 + g;
                uint32_t bf[2] = { sV[ks + tg][nc], sV[ks + tg + 4][nc] };
                mma8(acc[j], af, bf);
            }
        }
        __syncthreads();
    }

    const int b = bn >> 4, n = bn & 15;
    #pragma unroll
    for (int j = 0; j < 4; j++) {
        #pragma unroll
        for (int cr = 0; cr < 4; cr++) {
            int q = q0 + warpM * 16 + g + (cr >> 1) * 8;
            int h = warpN * 32 + j * 8 + tg * 2 + (cr & 1);
            g_O[(((size_t)b * SEQ + q) * NHEAD + n) * HS + h] = acc[j][cr];
        }
    }
}

// ---------------- 6) out = O @ (out_kernel * scale) + bias, tf32 mma ---------
__global__ __launch_bounds__(256) void proj_kernel(
    const float* __restrict__ wk, const float* __restrict__ bias,
    float* __restrict__ out)
{
    __shared__ uint32_t sA[128][20];
    __shared__ uint32_t sB[16][136];
    const int tid = threadIdx.x, lane = tid & 31, wid = tid >> 5;
    const int g = lane >> 2, tg = lane & 3;
    const int warpN = wid & 1, warpM = wid >> 1;
    const int m0 = blockIdx.y * 128, n0 = blockIdx.x * 128;

    float acc[2][8][4] = {};
    for (int k0 = 0; k0 < DM; k0 += 16) {
        #pragma unroll
        for (int t = 0; t < 2; t++) {
            int e = tid + t * 256;
            int r = e >> 2, c = (e & 3) * 4;
            float4 v = *(const float4*)&g_O[(size_t)(m0 + r) * DM + k0 + c];
            sA[r][c] = f2t(v.x); sA[r][c+1] = f2t(v.y);
            sA[r][c+2] = f2t(v.z); sA[r][c+3] = f2t(v.w);
            int rb = e >> 5, cb = (e & 31) * 4;
            float4 u = *(const float4*)&wk[(size_t)(k0 + rb) * DM + n0 + cb];
            sB[rb][cb] = f2t(u.x); sB[rb][cb+1] = f2t(u.y);
            sB[rb][cb+2] = f2t(u.z); sB[rb][cb+3] = f2t(u.w);
        }
        __syncthreads();
        #pragma unroll
        for (int ks = 0; ks < 16; ks += 8) {
            uint32_t af[2][4];
            #pragma unroll
            for (int i = 0; i < 2; i++) {
                int mr = warpM * 32 + i * 16;
                af[i][0] = sA[mr + g    ][ks + tg    ];
                af[i][1] = sA[mr + g + 8][ks + tg    ];
                af[i][2] = sA[mr + g    ][ks + tg + 4];
                af[i][3] = sA[mr + g + 8][ks + tg + 4];
            }
            #pragma unroll
            for (int j = 0; j < 8; j++) {
                int nc = warpN * 64 + j * 8 + g;
                uint32_t bf[2] = { sB[ks + tg][nc], sB[ks + tg + 4][nc] };
                #pragma unroll
                for (int i = 0; i < 2; i++) mma8(acc[i][j], af[i], bf);
            }
        }
        __syncthreads();
    }

    const float okscale = 0.03125f;   // (1024*1024)^-0.25 = 2^-5 exact
    #pragma unroll
    for (int i = 0; i < 2; i++) {
        #pragma unroll
        for (int j = 0; j < 8; j++) {
            #pragma unroll
            for (int cr = 0; cr < 4; cr++) {
                int m = m0 + warpM * 32 + i * 16 + g + (cr >> 1) * 8;
                int c = n0 + warpN * 64 + j * 8 + tg * 2 + (cr & 1);
                out[(size_t)m * DM + c] = acc[i][j][cr] * okscale + bias[c];
            }
        }
    }
}

// ---------------- launcher ---------------------------------------------------
extern "C" void kernel_launch(void* const* d_in, const int* in_sizes, int n_in,
                              void* d_out, int out_size)
{
    const float* inp = (const float*)d_in[0];   // (2, 2048, 1024)
    const float* qkv = (const float*)d_in[1];   // (1024, 3, 16, 64)
    const float* qb  = (const float*)d_in[2];   // (16, 64)
    const float* pos = (const float*)d_in[3];   // (256, 16, 64)
    const float* wk  = (const float*)d_in[4];   // (1024, 1024)
    const float* ob  = (const float*)d_in[5];   // (1024,)
    float* out = (float*)d_out;                 // (2, 2048, 1024)

    const int SC_SMEM = (64 * 72 + 192 * 72) * 4;   // 73728 B
    cudaFuncSetAttribute(scores_kernel,
                         cudaFuncAttributeMaxDynamicSharedMemorySize, SC_SMEM);

    qkv_kernel<<<dim3(BN3 / 128, (BATCH * SEQ) / 128), 256>>>(inp, qkv, qb);
    emb_kernel<<<SEQ, 256>>>(pos);
    scores_kernel<<<dim3(SEQ / 64, SEQ / 64, BATCH * NHEAD), 256, SC_SMEM>>>();
    softmax_kernel<<<dim3(SEQ, BATCH * NHEAD), 256>>>();
    av_kernel<<<dim3(SEQ / 64, BATCH * NHEAD), 256>>>();
    proj_kernel<<<dim3(DM / 128, (BATCH * SEQ) / 128), 256>>>(wk, ob, out);
}

// round 6
// speedup vs baseline: 2.6582x; 1.0787x over previous
#include <cuda_runtime.h>
#include <math.h>
#include <stdint.h>

#define BATCH 2
#define SEQ   2048
#define DM    1024
#define NHEAD 16
#define HS    64
#define FQ    256
#define BN3   3072   /* 3*NHEAD*HS */

// ---------------- scratch (device globals; no allocations allowed) ----------
__device__ float g_Q[BATCH*NHEAD*SEQ*HS];
__device__ float g_K[BATCH*NHEAD*SEQ*HS];
__device__ float g_V[BATCH*NHEAD*SEQ*HS];
__device__ float g_emb[NHEAD*SEQ*HS];
__device__ float g_O[BATCH*SEQ*NHEAD*HS];

// ---------------- tf32 mma helpers ------------------------------------------
__device__ __forceinline__ uint32_t f2t(float x) {
    uint32_t r; asm("cvt.rna.tf32.f32 %0, %1;" : "=r"(r) : "f"(x)); return r;
}
__device__ __forceinline__ void mma8(float c[4], const uint32_t a[4], const uint32_t b[2]) {
    asm volatile(
      "mma.sync.aligned.m16n8k8.row.col.f32.tf32.tf32.f32 "
      "{%0,%1,%2,%3}, {%4,%5,%6,%7}, {%8,%9}, {%0,%1,%2,%3};"
      : "+f"(c[0]), "+f"(c[1]), "+f"(c[2]), "+f"(c[3])
      : "r"(a[0]), "r"(a[1]), "r"(a[2]), "r"(a[3]), "r"(b[0]), "r"(b[1]));
}

// ---------------- 1) QKV projection: (4096x1024) @ (1024x3072), tf32 mma ----
__global__ __launch_bounds__(256) void qkv_kernel(
    const float* __restrict__ inp, const float* __restrict__ w,
    const float* __restrict__ qb)
{
    __shared__ uint32_t sA[128][20];
    __shared__ uint32_t sB[16][136];
    const int tid = threadIdx.x, lane = tid & 31, wid = tid >> 5;
    const int g = lane >> 2, tg = lane & 3;
    const int warpN = wid & 1, warpM = wid >> 1;
    const int m0 = blockIdx.y * 128, n0 = blockIdx.x * 128;

    float acc[2][8][4] = {};
    for (int k0 = 0; k0 < DM; k0 += 16) {
        #pragma unroll
        for (int t = 0; t < 2; t++) {
            int e = tid + t * 256;
            int r = e >> 2, c = (e & 3) * 4;
            float4 v = *(const float4*)&inp[(size_t)(m0 + r) * DM + k0 + c];
            sA[r][c] = f2t(v.x); sA[r][c+1] = f2t(v.y);
            sA[r][c+2] = f2t(v.z); sA[r][c+3] = f2t(v.w);
            int rb = e >> 5, cb = (e & 31) * 4;
            float4 u = *(const float4*)&w[(size_t)(k0 + rb) * BN3 + n0 + cb];
            sB[rb][cb] = f2t(u.x); sB[rb][cb+1] = f2t(u.y);
            sB[rb][cb+2] = f2t(u.z); sB[rb][cb+3] = f2t(u.w);
        }
        __syncthreads();
        #pragma unroll
        for (int ks = 0; ks < 16; ks += 8) {
            uint32_t af[2][4];
            #pragma unroll
            for (int i = 0; i < 2; i++) {
                int mr = warpM * 32 + i * 16;
                af[i][0] = sA[mr + g    ][ks + tg    ];
                af[i][1] = sA[mr + g + 8][ks + tg    ];
                af[i][2] = sA[mr + g    ][ks + tg + 4];
                af[i][3] = sA[mr + g + 8][ks + tg + 4];
            }
            #pragma unroll
            for (int j = 0; j < 8; j++) {
                int nc = warpN * 64 + j * 8 + g;
                uint32_t bf[2] = { sB[ks + tg][nc], sB[ks + tg + 4][nc] };
                #pragma unroll
                for (int i = 0; i < 2; i++) mma8(acc[i][j], af[i], bf);
            }
        }
        __syncthreads();
    }

    const float qscale = powf(3.0f * DM * NHEAD * HS, -0.25f);
    #pragma unroll
    for (int i = 0; i < 2; i++) {
        #pragma unroll
        for (int j = 0; j < 8; j++) {
            #pragma unroll
            for (int cr = 0; cr < 4; cr++) {
                int m = m0 + warpM * 32 + i * 16 + g + (cr >> 1) * 8;
                int c = n0 + warpN * 64 + j * 8 + tg * 2 + (cr & 1);
                int b = m >> 11, s = m & (SEQ - 1);
                int A = c >> 10, n = (c >> 6) & 15, h = c & 63;
                float v = acc[i][j][cr] * qscale;
                size_t dst = ((size_t)(b * NHEAD + n) * SEQ + s) * HS + h;
                if (A == 0)      g_Q[dst] = v + qb[n * HS + h];
                else if (A == 1) g_K[dst] = v;
                else             g_V[dst] = v;
            }
        }
    }
}

// ---------------- 2) relative-position embedding table ----------------------
__global__ __launch_bounds__(256) void emb_kernel(const float* __restrict__ pos)
{
    __shared__ float ssin[FQ];
    const int s = blockIdx.x;
    const int tid = threadIdx.x;
    {
        int f = tid;
        double inv = pow(10000.0, -(double)((f >> 1) * 2) / (double)FQ);
        double ang = (double)s * inv;
        double v = (f & 1) ? cos(ang) : sin(ang);
        ssin[f] = (float)(1.4142135623730951 * v);
    }
    __syncthreads();

    int c4 = tid * 4;
    float a0 = 0.f, a1 = 0.f, a2 = 0.f, a3 = 0.f;
    for (int f = 0; f < FQ; f++) {
        float4 p = *reinterpret_cast<const float4*>(&pos[(size_t)f * (NHEAD * HS) + c4]);
        float sv = ssin[f];
        a0 += sv * p.x; a1 += sv * p.y; a2 += sv * p.z; a3 += sv * p.w;
    }
    const float pscale = 0.0625f;
    int n = c4 >> 6, h = c4 & 63;
    size_t base = ((size_t)n * SEQ + s) * HS + h;
    g_emb[base + 0] = a0 * pscale;
    g_emb[base + 1] = a1 * pscale;
    g_emb[base + 2] = a2 * pscale;
    g_emb[base + 3] = a3 * pscale;
}

// ---------------- 3) fused flash attention ----------------------------------
// Per (bn, q-tile of 64): stream k-tiles, online softmax, accumulate O.
// SMEM words:
//   sQ   [64][72]  tf32, persistent                     @ 0
//   sKE  [192][72] tf32 (K rows 0-63, E rows 64-191)    @ 4608
//     stage2 alias: sC [64][72] fp32 @ 4608 ; sP [64][132] fp32 @ 9216
//   sV   [64][72]  tf32                                 @ 18432
//   m_s/l_s/rs [64] each                                @ 23040
extern __shared__ uint32_t smw[];
__global__ __launch_bounds__(256) void attn_kernel()
{
    const int qt = (SEQ / 64 - 1) - blockIdx.x;   // longest blocks first
    const int bn = blockIdx.y;
    const int q0 = qt * 64;

    uint32_t* sQ  = smw;
    uint32_t* sKE = smw + 4608;
    float*    sC  = (float*)(smw + 4608);
    uint32_t* sCu = smw + 4608;
    float*    sP  = (float*)(smw + 9216);
    uint32_t* sV  = smw + 18432;
    float*    m_s = (float*)(smw + 23040);
    float*    l_s = m_s + 64;
    float*    rs  = m_s + 128;

    const float* Qg = g_Q + (size_t)bn * SEQ * HS;
    const float* Kg = g_K + (size_t)bn * SEQ * HS;
    const float* Vg = g_V + (size_t)bn * SEQ * HS;
    const int hd = bn & (NHEAD - 1);
    const float* Eg = g_emb + (size_t)hd * SEQ * HS;

    const int tid = threadIdx.x, lane = tid & 31, wid = tid >> 5;
    const int g = lane >> 2, tg = lane & 3;
    // QK phase warp grid: 2 x 4 (warp tile 32x48 of 64x192)
    const int wMs = wid & 1, wNs = wid >> 1;
    // PV phase warp grid: 4 x 2 (warp tile 16x32 of 64x64)
    const int wMo = wid & 3, wNo = wid >> 2;
    // softmax mapping: 4 threads per row
    const int srow = tid >> 2, sq4 = tid & 3;

    // load Q tile (persistent) + init state
    #pragma unroll
    for (int t = 0; t < 4; t++) {
        int e = tid + t * 256;
        int r = e >> 4, c = (e & 15) * 4;
        float4 v = *(const float4*)&Qg[(size_t)(q0 + r) * HS + c];
        sQ[r * 72 + c] = f2t(v.x); sQ[r * 72 + c + 1] = f2t(v.y);
        sQ[r * 72 + c + 2] = f2t(v.z); sQ[r * 72 + c + 3] = f2t(v.w);
    }
    if (tid < 64) { m_s[tid] = -1e30f; l_s[tid] = 0.f; }

    float acc_o[4][4] = {};

    for (int kt = 0; kt <= qt; kt++) {
        const int k0 = kt * 64;
        int dlo = q0 - k0 - 63; if (dlo < 0) dlo = 0;

        __syncthreads();   // prior iteration's PV reads of sC/sV complete

        // ---- load K (rows 0-63) + E window (rows 64-191) + V ----
        #pragma unroll
        for (int t = 0; t < 12; t++) {
            int e = tid + t * 256;
            int r = e >> 4, c = (e & 15) * 4;
            float4 v;
            if (r < 64) {
                v = *(const float4*)&Kg[(size_t)(k0 + r) * HS + c];
            } else {
                int d = dlo + r - 64;
                if (d < SEQ) v = *(const float4*)&Eg[(size_t)d * HS + c];
                else         v = make_float4(0.f, 0.f, 0.f, 0.f);
            }
            sKE[r * 72 + c] = f2t(v.x); sKE[r * 72 + c + 1] = f2t(v.y);
            sKE[r * 72 + c + 2] = f2t(v.z); sKE[r * 72 + c + 3] = f2t(v.w);
        }
        #pragma unroll
        for (int t = 0; t < 4; t++) {
            int e = tid + t * 256;
            int r = e >> 4, c = (e & 15) * 4;
            float4 u = *(const float4*)&Vg[(size_t)(k0 + r) * HS + c];
            sV[r * 72 + c] = f2t(u.x); sV[r * 72 + c + 1] = f2t(u.y);
            sV[r * 72 + c + 2] = f2t(u.z); sV[r * 72 + c + 3] = f2t(u.w);
        }
        __syncthreads();

        // ---- fused QK^T / Q@E^T MMA: 64 x 192 ----
        float acc_s[2][6][4] = {};
        #pragma unroll
        for (int ks = 0; ks < HS; ks += 8) {
            uint32_t af[2][4];
            #pragma unroll
            for (int i = 0; i < 2; i++) {
                int mr = wMs * 32 + i * 16;
                af[i][0] = sQ[(mr + g    ) * 72 + ks + tg    ];
                af[i][1] = sQ[(mr + g + 8) * 72 + ks + tg    ];
                af[i][2] = sQ[(mr + g    ) * 72 + ks + tg + 4];
                af[i][3] = sQ[(mr + g + 8) * 72 + ks + tg + 4];
            }
            #pragma unroll
            for (int j = 0; j < 6; j++) {
                int nc = wNs * 48 + j * 8 + g;
                uint32_t bf[2] = { sKE[nc * 72 + ks + tg], sKE[nc * 72 + ks + tg + 4] };
                #pragma unroll
                for (int i = 0; i < 2; i++) mma8(acc_s[i][j], af[i], bf);
            }
        }
        __syncthreads();   // all sKE reads done -> reuse region as sC/sP

        #pragma unroll
        for (int i = 0; i < 2; i++) {
            #pragma unroll
            for (int j = 0; j < 6; j++) {
                #pragma unroll
                for (int cr = 0; cr < 4; cr++) {
                    int row = wMs * 32 + i * 16 + g + (cr >> 1) * 8;
                    int col = wNs * 48 + j * 8 + tg * 2 + (cr & 1);
                    float v = acc_s[i][j][cr];
                    if (col < 64) sC[row * 72 + col] = v;
                    else          sP[row * 132 + (col - 64)] = v;
                }
            }
        }
        __syncthreads();

        // ---- gather + online softmax (4 threads per row, 16 cols each) ----
        {
            const int q = q0 + srow;
            const float m_old = m_s[srow];
            const bool diag = (kt == qt);
            float sv[16];
            float tmax = -1e30f;
            #pragma unroll
            for (int i = 0; i < 16; i++) {
                int c = sq4 * 16 + i;
                int k = k0 + c;
                float x;
                if (diag && k > q) x = -1e30f;
                else x = (sC[srow * 72 + c] + sP[srow * 132 + (q - k - dlo)]) * 0.125f;
                sv[i] = x;
                tmax = fmaxf(tmax, x);
            }
            tmax = fmaxf(tmax, __shfl_xor_sync(0xffffffffu, tmax, 1));
            tmax = fmaxf(tmax, __shfl_xor_sync(0xffffffffu, tmax, 2));
            const float m_new = fmaxf(m_old, tmax);
            float sum = 0.f;
            #pragma unroll
            for (int i = 0; i < 16; i++) {
                float p = __expf(sv[i] - m_new);
                sum += p;
                sC[srow * 72 + sq4 * 16 + i] = __uint_as_float(f2t(p));
            }
            sum += __shfl_xor_sync(0xffffffffu, sum, 1);
            sum += __shfl_xor_sync(0xffffffffu, sum, 2);
            if (sq4 == 0) {
                float sc = __expf(m_old - m_new);
                rs[srow]  = sc;
                m_s[srow] = m_new;
                l_s[srow] = l_s[srow] * sc + sum;
            }
        }
        __syncthreads();

        // ---- rescale O accumulator, then P @ V ----
        {
            const float s0 = rs[wMo * 16 + g];
            const float s1 = rs[wMo * 16 + g + 8];
            #pragma unroll
            for (int j = 0; j < 4; j++) {
                acc_o[j][0] *= s0; acc_o[j][1] *= s0;
                acc_o[j][2] *= s1; acc_o[j][3] *= s1;
            }
            #pragma unroll
            for (int ks = 0; ks < 64; ks += 8) {
                uint32_t af[4];
                int mr = wMo * 16;
                af[0] = sCu[(mr + g    ) * 72 + ks + tg    ];
                af[1] = sCu[(mr + g + 8) * 72 + ks + tg    ];
                af[2] = sCu[(mr + g    ) * 72 + ks + tg + 4];
                af[3] = sCu[(mr + g + 8) * 72 + ks + tg + 4];
                #pragma unroll
                for (int j = 0; j < 4; j++) {
                    int nc = wNo * 32 + j * 8 + g;
                    uint32_t bf[2] = { sV[(ks + tg) * 72 + nc], sV[(ks + tg + 4) * 72 + nc] };
                    mma8(acc_o[j], af, bf);
                }
            }
        }
    }

    // ---- epilogue: divide by l, store ----
    const int b = bn >> 4, n = bn & 15;
    const float inv0 = 1.f / l_s[wMo * 16 + g];
    const float inv1 = 1.f / l_s[wMo * 16 + g + 8];
    #pragma unroll
    for (int j = 0; j < 4; j++) {
        #pragma unroll
        for (int cr = 0; cr < 4; cr++) {
            int q = q0 + wMo * 16 + g + (cr >> 1) * 8;
            int h = wNo * 32 + j * 8 + tg * 2 + (cr & 1);
            g_O[(((size_t)b * SEQ + q) * NHEAD + n) * HS + h] =
                acc_o[j][cr] * ((cr >> 1) ? inv1 : inv0);
        }
    }
}

// ---------------- 4) out = O @ (out_kernel * scale) + bias, tf32 mma ---------
__global__ __launch_bounds__(256) void proj_kernel(
    const float* __restrict__ wk, const float* __restrict__ bias,
    float* __restrict__ out)
{
    __shared__ uint32_t sA[128][20];
    __shared__ uint32_t sB[16][136];
    const int tid = threadIdx.x, lane = tid & 31, wid = tid >> 5;
    const int g = lane >> 2, tg = lane & 3;
    const int warpN = wid & 1, warpM = wid >> 1;
    const int m0 = blockIdx.y * 128, n0 = blockIdx.x * 128;

    float acc[2][8][4] = {};
    for (int k0 = 0; k0 < DM; k0 += 16) {
        #pragma unroll
        for (int t = 0; t < 2; t++) {
            int e = tid + t * 256;
            int r = e >> 2, c = (e & 3) * 4;
            float4 v = *(const float4*)&g_O[(size_t)(m0 + r) * DM + k0 + c];
            sA[r][c] = f2t(v.x); sA[r][c+1] = f2t(v.y);
            sA[r][c+2] = f2t(v.z); sA[r][c+3] = f2t(v.w);
            int rb = e >> 5, cb = (e & 31) * 4;
            float4 u = *(const float4*)&wk[(size_t)(k0 + rb) * DM + n0 + cb];
            sB[rb][cb] = f2t(u.x); sB[rb][cb+1] = f2t(u.y);
            sB[rb][cb+2] = f2t(u.z); sB[rb][cb+3] = f2t(u.w);
        }
        __syncthreads();
        #pragma unroll
        for (int ks = 0; ks < 16; ks += 8) {
            uint32_t af[2][4];
            #pragma unroll
            for (int i = 0; i < 2; i++) {
                int mr = warpM * 32 + i * 16;
                af[i][0] = sA[mr + g    ][ks + tg    ];
                af[i][1] = sA[mr + g + 8][ks + tg    ];
                af[i][2] = sA[mr + g    ][ks + tg + 4];
                af[i][3] = sA[mr + g + 8][ks + tg + 4];
            }
            #pragma unroll
            for (int j = 0; j < 8; j++) {
                int nc = warpN * 64 + j * 8 + g;
                uint32_t bf[2] = { sB[ks + tg][nc], sB[ks + tg + 4][nc] };
                #pragma unroll
                for (int i = 0; i < 2; i++) mma8(acc[i][j], af[i], bf);
            }
        }
        __syncthreads();
    }

    const float okscale = 0.03125f;   // (1024*1024)^-0.25
    #pragma unroll
    for (int i = 0; i < 2; i++) {
        #pragma unroll
        for (int j = 0; j < 8; j++) {
            #pragma unroll
            for (int cr = 0; cr < 4; cr++) {
                int m = m0 + warpM * 32 + i * 16 + g + (cr >> 1) * 8;
                int c = n0 + warpN * 64 + j * 8 + tg * 2 + (cr & 1);
                out[(size_t)m * DM + c] = acc[i][j][cr] * okscale + bias[c];
            }
        }
    }
}

// ---------------- launcher ---------------------------------------------------
extern "C" void kernel_launch(void* const* d_in, const int* in_sizes, int n_in,
                              void* d_out, int out_size)
{
    const float* inp = (const float*)d_in[0];   // (2, 2048, 1024)
    const float* qkv = (const float*)d_in[1];   // (1024, 3, 16, 64)
    const float* qb  = (const float*)d_in[2];   // (16, 64)
    const float* pos = (const float*)d_in[3];   // (256, 16, 64)
    const float* wk  = (const float*)d_in[4];   // (1024, 1024)
    const float* ob  = (const float*)d_in[5];   // (1024,)
    float* out = (float*)d_out;                 // (2, 2048, 1024)

    const int AT_SMEM = 23232 * 4;   // 92928 B
    cudaFuncSetAttribute(attn_kernel,
                         cudaFuncAttributeMaxDynamicSharedMemorySize, AT_SMEM);

    qkv_kernel<<<dim3(BN3 / 128, (BATCH * SEQ) / 128), 256>>>(inp, qkv, qb);
    emb_kernel<<<SEQ, 256>>>(pos);
    attn_kernel<<<dim3(SEQ / 64, BATCH * NHEAD), 256, AT_SMEM>>>();
    proj_kernel<<<dim3(DM / 128, (BATCH * SEQ) / 128), 256>>>(wk, ob, out);
}